// round 14
// baseline (speedup 1.0000x reference)
#include <cuda_runtime.h>
#include <cstdint>

#define IMG_N  2048
#define OW     2044
#define OH     2044
#define TW     128
#define TH     16          // output rows per CTA (2 per thread)
#define IR     20          // TH + 4 input rows
#define IC     132         // TW + 4 input cols
#define ICP    136         // padded col stride (bf16) for staged planes
#define NTH    256

// smem layout (bytes)
#define SX_OFF     0
#define SX_BYTES   (IR * IC * 4)               // 10560: raw int tile
#define PL_OFF     SX_BYTES                    // bf16 planes [IR][7][ICP]
#define PL_BYTES   (IR * 7 * ICP * 2)          // 38080
#define SMEM_BYTES (PL_OFF + PL_BYTES)         // 48640

typedef unsigned long long ull;
typedef unsigned int u32;

__constant__ float c_w[75];                     // weight[d][i][j] = d*25+i*5+j

__device__ __forceinline__ void fma2(ull& acc, ull a, ull b) {
    asm("fma.rn.f32x2 %0, %1, %2, %0;" : "+l"(acc) : "l"(a), "l"(b));
}
__device__ __forceinline__ ull dup2(float w) {
    ull r; asm("mov.b64 %0, {%1, %1};" : "=l"(r) : "f"(w)); return r;
}
__device__ __forceinline__ ull mkpair_lohi(u32 u) {
    ull r;
    asm("{.reg .b32 a, b;\n\t"
        "shl.b32 a, %1, 16;\n\t"
        "and.b32 b, %1, 0xFFFF0000;\n\t"
        "mov.b64 %0, {a, b};}" : "=l"(r) : "r"(u));
    return r;
}
__device__ __forceinline__ ull mkpair_cross(u32 u, u32 v) {
    ull r;
    asm("{.reg .b32 a, b;\n\t"
        "and.b32 a, %1, 0xFFFF0000;\n\t"
        "shl.b32 b, %2, 16;\n\t"
        "mov.b64 %0, {a, b};}" : "=l"(r) : "r"(u), "r"(v));
    return r;
}

// Expand np bit-planes [z0, z0+np) of the int tile into bf16 planes (exact).
__device__ __forceinline__ void expand_planes(const int* __restrict__ sx,
                                              uint16_t* __restrict__ pl,
                                              int tid, int z0, int np)
{
    for (int idx = tid; idx < IR * (IC / 2); idx += NTH) {
        int rr = idx / (IC / 2);
        int c2 = (idx - rr * (IC / 2)) * 2;
        const int* src = sx + rr * IC + c2;
        u32 v0 = (u32)src[0] >> z0;
        u32 v1 = (u32)src[1] >> z0;
        u32* dst = reinterpret_cast<u32*>(pl + (rr * 7) * ICP + c2);
        #pragma unroll 7
        for (int p = 0; p < np; p++) {
            u32 val = ((v0 >> p) & 1u) * 0x3F80u
                    | ((v1 >> p) & 1u) * 0x3F800000u;
            dst[p * (ICP / 2)] = val;
        }
    }
}

// 10 FMA2s for one tap-row into one output-row's accumulators.
// Weights come from the constant bank (uniform path, no RF pairs, no LDS).
__device__ __forceinline__ void tap_row(ull& aA, ull& aB,
                                        const float* __restrict__ wrow,
                                        const ull* S)
{
    ull w0 = dup2(wrow[0]), w1 = dup2(wrow[1]), w2 = dup2(wrow[2]);
    ull w3 = dup2(wrow[3]), w4 = dup2(wrow[4]);
    fma2(aA, w0, S[0]);  fma2(aB, w0, S[2]);
    fma2(aA, w1, S[1]);  fma2(aB, w1, S[3]);
    fma2(aA, w2, S[2]);  fma2(aB, w2, S[4]);
    fma2(aA, w3, S[3]);  fma2(aB, w3, S[5]);
    fma2(aA, w4, S[4]);  fma2(aB, w4, S[6]);
}

// One z-pass: NZ outputs for TWO adjacent output rows (2*rp, 2*rp+1).
// S pairs loaded+packed once per (input row, kk), shared by both rows.
template<int NZ>
__device__ __forceinline__ void run_pass(const uint16_t* __restrict__ pl,
                                         int rp, int col0,
                                         ull a0A[], ull a0B[], ull a1A[], ull a1B[])
{
    #pragma unroll
    for (int z = 0; z < NZ; z++) {
        a0A[z] = 0ull; a0B[z] = 0ull; a1A[z] = 0ull; a1B[z] = 0ull;
    }

    #pragma unroll 1
    for (int ri = 0; ri < 6; ri++) {            // input row = 2*rp + ri
        const uint16_t* rowp = pl + ((2 * rp + ri) * 7) * ICP + col0;
        const int i0 = ri;                       // tap row for output row 0
        const int i1 = ri - 1;                   // tap row for output row 1
        const bool use0 = (ri <= 4);
        const bool use1 = (ri >= 1);

        #pragma unroll
        for (int kk = 0; kk < NZ + 2; kk++) {
            const u32* rk = reinterpret_cast<const u32*>(rowp + kk * ICP);
            uint2 ma = *reinterpret_cast<const uint2*>(rk);       // bf16 cols 0..3
            uint2 mb = *reinterpret_cast<const uint2*>(rk + 2);   // bf16 cols 4..7

            ull S[7];
            S[0] = mkpair_lohi (ma.x);
            S[1] = mkpair_cross(ma.x, ma.y);
            S[2] = mkpair_lohi (ma.y);
            S[3] = mkpair_cross(ma.y, mb.x);
            S[4] = mkpair_lohi (mb.x);
            S[5] = mkpair_cross(mb.x, mb.y);
            S[6] = mkpair_lohi (mb.y);

            #pragma unroll
            for (int d = 0; d < 3; d++) {
                const int zz = kk - d;                   // compile-time
                if (zz >= 0 && zz < NZ) {
                    if (use0)
                        tap_row(a0A[zz], a0B[zz], c_w + d * 25 + i0 * 5, S);
                    if (use1)
                        tap_row(a1A[zz], a1B[zz], c_w + d * 25 + i1 * 5, S);
                }
            }
        }
    }
}

__device__ __forceinline__ void store_row(float* __restrict__ out, int h, int w,
                                          int z0, int nz, float bv,
                                          const ull* accA, const ull* accB)
{
    if (h >= OH || w >= OW) return;
    const bool full = (w + 4 <= OW);
    for (int zz = 0; zz < nz; zz++) {
        float2 a = *reinterpret_cast<const float2*>(&accA[zz]);
        float2 b = *reinterpret_cast<const float2*>(&accB[zz]);
        size_t off = ((size_t)(z0 + zz) * OH + h) * OW + w;
        if (full) {
            *reinterpret_cast<float4*>(out + off) =
                make_float4(a.x + bv, a.y + bv, b.x + bv, b.y + bv);
        } else {
            float vals[4] = { a.x + bv, a.y + bv, b.x + bv, b.y + bv };
            #pragma unroll
            for (int c = 0; c < 4; c++)
                if (w + c < OW) out[off + c] = vals[c];
        }
    }
}

__global__ void __launch_bounds__(NTH, 3)
conv2dto3d_kernel(const int* __restrict__ x,
                  const float* __restrict__ bias,
                  float* __restrict__ out)
{
    extern __shared__ unsigned char smem[];
    int*       sx = reinterpret_cast<int*>(smem + SX_OFF);
    uint16_t*  pl = reinterpret_cast<uint16_t*>(smem + PL_OFF);

    const int tid   = threadIdx.x;
    const int wbase = blockIdx.x * TW;
    const int hbase = blockIdx.y * TH;

    // ---- load int tile (clamped) ----
    for (int idx = tid; idx < IR * IC; idx += NTH) {
        int rr = idx / IC, cc = idx - rr * IC;
        int ri = hbase + rr; if (ri > IMG_N - 1) ri = IMG_N - 1;
        int ci = wbase + cc; if (ci > IMG_N - 1) ci = IMG_N - 1;
        sx[idx] = x[ri * IMG_N + ci];
    }
    __syncthreads();

    const int g  = tid & 31;         // 32 column groups of 4
    const int rp = tid >> 5;         // row pair 0..7 -> output rows 2rp, 2rp+1
    const int col0 = g * 4;
    const int h0 = hbase + 2 * rp;
    const int w  = wbase + col0;
    const float bv = bias[0];

    ull a0A[5], a0B[5], a1A[5], a1B[5];

    // ---- pass 0: z in [0..4], planes 0..6 ----
    expand_planes(sx, pl, tid, 0, 7);
    __syncthreads();
    run_pass<5>(pl, rp, col0, a0A, a0B, a1A, a1B);
    __syncthreads();
    store_row(out, h0,     w, 0, 5, bv, a0A, a0B);
    store_row(out, h0 + 1, w, 0, 5, bv, a1A, a1B);

    // ---- pass 1: z in [5..9], planes 5..11 ----
    expand_planes(sx, pl, tid, 5, 7);
    __syncthreads();
    run_pass<5>(pl, rp, col0, a0A, a0B, a1A, a1B);
    __syncthreads();
    store_row(out, h0,     w, 5, 5, bv, a0A, a0B);
    store_row(out, h0 + 1, w, 5, 5, bv, a1A, a1B);

    // ---- pass 2: z in [10..13], planes 10..15 ----
    expand_planes(sx, pl, tid, 10, 6);
    __syncthreads();
    run_pass<4>(pl, rp, col0, a0A, a0B, a1A, a1B);
    store_row(out, h0,     w, 10, 4, bv, a0A, a0B);
    store_row(out, h0 + 1, w, 10, 4, bv, a1A, a1B);
}

extern "C" void kernel_launch(void* const* d_in, const int* in_sizes, int n_in,
                              void* d_out, int out_size)
{
    const int*   x      = (const int*)d_in[0];
    const float* weight = (const float*)d_in[1];
    const float* bias   = (const float*)d_in[2];
    float*       out    = (float*)d_out;

    cudaMemcpyToSymbolAsync(c_w, weight, 75 * sizeof(float), 0,
                            cudaMemcpyDeviceToDevice, 0);

    cudaFuncSetAttribute(conv2dto3d_kernel,
                         cudaFuncAttributeMaxDynamicSharedMemorySize, SMEM_BYTES);

    dim3 grid((OW + TW - 1) / TW, (OH + TH - 1) / TH);   // 16 x 128
    conv2dto3d_kernel<<<grid, NTH, SMEM_BYTES>>>(x, bias, out);
}

// round 15
// speedup vs baseline: 1.0665x; 1.0665x over previous
#include <cuda_runtime.h>
#include <cstdint>

#define IMG_N  2048
#define OW     2044
#define OH     2044
#define TW     128
#define TH     16          // output rows per CTA (2 per thread)
#define IR     20          // TH + 4 input rows
#define IC     132         // TW + 4 input cols
#define ICP    136         // padded col stride (bf16) for staged planes
#define NTH    256

// smem layout (bytes)
#define SX_OFF     0
#define SX_BYTES   (IR * IC * 4)               // 10560: raw int tile
#define PL_OFF     SX_BYTES                    // bf16 planes [IR][7][ICP]
#define PL_BYTES   (IR * 7 * ICP * 2)          // 38080
#define SMEM_BYTES (PL_OFF + PL_BYTES)         // 48640

typedef unsigned long long ull;
typedef unsigned int u32;

// weight pairs {w,w}, d*25+i*5+j — filled by two strided D2D 2D-copies
__constant__ float2 c_wp[75];

__device__ __forceinline__ void fma2(ull& acc, ull a, ull b) {
    asm("fma.rn.f32x2 %0, %1, %2, %0;" : "+l"(acc) : "l"(a), "l"(b));
}
// one LDCU.64 -> UR pair
__device__ __forceinline__ ull wpair(int idx) {
    float2 p = c_wp[idx];
    return *reinterpret_cast<ull*>(&p);
}
__device__ __forceinline__ ull mkpair_lohi(u32 u) {
    ull r;
    asm("{.reg .b32 a, b;\n\t"
        "shl.b32 a, %1, 16;\n\t"
        "and.b32 b, %1, 0xFFFF0000;\n\t"
        "mov.b64 %0, {a, b};}" : "=l"(r) : "r"(u));
    return r;
}
__device__ __forceinline__ ull mkpair_cross(u32 u, u32 v) {
    ull r;
    asm("{.reg .b32 a, b;\n\t"
        "and.b32 a, %1, 0xFFFF0000;\n\t"
        "shl.b32 b, %2, 16;\n\t"
        "mov.b64 %0, {a, b};}" : "=l"(r) : "r"(u), "r"(v));
    return r;
}

// Expand np bit-planes [z0, z0+np) of the int tile into bf16 planes (exact).
__device__ __forceinline__ void expand_planes(const int* __restrict__ sx,
                                              uint16_t* __restrict__ pl,
                                              int tid, int z0, int np)
{
    for (int idx = tid; idx < IR * (IC / 2); idx += NTH) {
        int rr = idx / (IC / 2);
        int c2 = (idx - rr * (IC / 2)) * 2;
        const int* src = sx + rr * IC + c2;
        u32 v0 = (u32)src[0] >> z0;
        u32 v1 = (u32)src[1] >> z0;
        u32* dst = reinterpret_cast<u32*>(pl + (rr * 7) * ICP + c2);
        #pragma unroll 7
        for (int p = 0; p < np; p++) {
            u32 val = ((v0 >> p) & 1u) * 0x3F80u
                    | ((v1 >> p) & 1u) * 0x3F800000u;
            dst[p * (ICP / 2)] = val;
        }
    }
}

// 10 FMA2s for one tap-row into one output-row's accumulators.
__device__ __forceinline__ void tap_row(ull& aA, ull& aB, const ull* wv, const ull* S)
{
    fma2(aA, wv[0], S[0]);  fma2(aB, wv[0], S[2]);
    fma2(aA, wv[1], S[1]);  fma2(aB, wv[1], S[3]);
    fma2(aA, wv[2], S[2]);  fma2(aB, wv[2], S[4]);
    fma2(aA, wv[3], S[3]);  fma2(aB, wv[3], S[5]);
    fma2(aA, wv[4], S[4]);  fma2(aB, wv[4], S[6]);
}

// One z-pass: NZ outputs for TWO adjacent output rows (2*rp, 2*rp+1).
// S pairs loaded+packed once per (input row, kk), shared by both rows.
// Weight pairs hoisted per-ri (LDCU.64 -> UR pairs).
template<int NZ>
__device__ __forceinline__ void run_pass(const uint16_t* __restrict__ pl,
                                         int rp, int col0,
                                         ull a0A[], ull a0B[], ull a1A[], ull a1B[])
{
    #pragma unroll
    for (int z = 0; z < NZ; z++) {
        a0A[z] = 0ull; a0B[z] = 0ull; a1A[z] = 0ull; a1B[z] = 0ull;
    }

    #pragma unroll 1
    for (int ri = 0; ri < 6; ri++) {            // input row = 2*rp + ri
        const uint16_t* rowp = pl + ((2 * rp + ri) * 7) * ICP + col0;
        const int i0 = ri;                       // tap row for output row 0
        const int i1 = ri - 1;                   // tap row for output row 1
        const bool use0 = (ri <= 4);
        const bool use1 = (ri >= 1);

        // hoist weight pairs for both tap rows (uniform path)
        ull wv0[15], wv1[15];
        #pragma unroll
        for (int d = 0; d < 3; d++)
            #pragma unroll
            for (int j = 0; j < 5; j++) {
                wv0[d * 5 + j] = use0 ? wpair(d * 25 + i0 * 5 + j) : 0ull;
                wv1[d * 5 + j] = use1 ? wpair(d * 25 + i1 * 5 + j) : 0ull;
            }

        #pragma unroll
        for (int kk = 0; kk < NZ + 2; kk++) {
            const u32* rk = reinterpret_cast<const u32*>(rowp + kk * ICP);
            uint2 ma = *reinterpret_cast<const uint2*>(rk);       // bf16 cols 0..3
            uint2 mb = *reinterpret_cast<const uint2*>(rk + 2);   // bf16 cols 4..7

            ull S[7];
            S[0] = mkpair_lohi (ma.x);
            S[1] = mkpair_cross(ma.x, ma.y);
            S[2] = mkpair_lohi (ma.y);
            S[3] = mkpair_cross(ma.y, mb.x);
            S[4] = mkpair_lohi (mb.x);
            S[5] = mkpair_cross(mb.x, mb.y);
            S[6] = mkpair_lohi (mb.y);

            #pragma unroll
            for (int d = 0; d < 3; d++) {
                const int zz = kk - d;                   // compile-time
                if (zz >= 0 && zz < NZ) {
                    if (use0) tap_row(a0A[zz], a0B[zz], wv0 + d * 5, S);
                    if (use1) tap_row(a1A[zz], a1B[zz], wv1 + d * 5, S);
                }
            }
        }
    }
}

__device__ __forceinline__ void store_row(float* __restrict__ out, int h, int w,
                                          int z0, int nz, float bv,
                                          const ull* accA, const ull* accB)
{
    if (h >= OH || w >= OW) return;
    const bool full = (w + 4 <= OW);
    for (int zz = 0; zz < nz; zz++) {
        float2 a = *reinterpret_cast<const float2*>(&accA[zz]);
        float2 b = *reinterpret_cast<const float2*>(&accB[zz]);
        size_t off = ((size_t)(z0 + zz) * OH + h) * OW + w;
        if (full) {
            *reinterpret_cast<float4*>(out + off) =
                make_float4(a.x + bv, a.y + bv, b.x + bv, b.y + bv);
        } else {
            float vals[4] = { a.x + bv, a.y + bv, b.x + bv, b.y + bv };
            #pragma unroll
            for (int c = 0; c < 4; c++)
                if (w + c < OW) out[off + c] = vals[c];
        }
    }
}

__global__ void __launch_bounds__(NTH, 4)
conv2dto3d_kernel(const int* __restrict__ x,
                  const float* __restrict__ bias,
                  float* __restrict__ out)
{
    extern __shared__ unsigned char smem[];
    int*       sx = reinterpret_cast<int*>(smem + SX_OFF);
    uint16_t*  pl = reinterpret_cast<uint16_t*>(smem + PL_OFF);

    const int tid   = threadIdx.x;
    const int wbase = blockIdx.x * TW;
    const int hbase = blockIdx.y * TH;

    // ---- load int tile (clamped) ----
    for (int idx = tid; idx < IR * IC; idx += NTH) {
        int rr = idx / IC, cc = idx - rr * IC;
        int ri = hbase + rr; if (ri > IMG_N - 1) ri = IMG_N - 1;
        int ci = wbase + cc; if (ci > IMG_N - 1) ci = IMG_N - 1;
        sx[idx] = x[ri * IMG_N + ci];
    }
    __syncthreads();

    const int g  = tid & 31;         // 32 column groups of 4
    const int rp = tid >> 5;         // row pair 0..7 -> output rows 2rp, 2rp+1
    const int col0 = g * 4;
    const int h0 = hbase + 2 * rp;
    const int w  = wbase + col0;
    const float bv = bias[0];

    ull a0A[5], a0B[5], a1A[5], a1B[5];

    // ---- pass 0: z in [0..4], planes 0..6 ----
    expand_planes(sx, pl, tid, 0, 7);
    __syncthreads();
    run_pass<5>(pl, rp, col0, a0A, a0B, a1A, a1B);
    __syncthreads();
    store_row(out, h0,     w, 0, 5, bv, a0A, a0B);
    store_row(out, h0 + 1, w, 0, 5, bv, a1A, a1B);

    // ---- pass 1: z in [5..9], planes 5..11 ----
    expand_planes(sx, pl, tid, 5, 7);
    __syncthreads();
    run_pass<5>(pl, rp, col0, a0A, a0B, a1A, a1B);
    __syncthreads();
    store_row(out, h0,     w, 5, 5, bv, a0A, a0B);
    store_row(out, h0 + 1, w, 5, 5, bv, a1A, a1B);

    // ---- pass 2: z in [10..13], planes 10..15 ----
    expand_planes(sx, pl, tid, 10, 6);
    __syncthreads();
    run_pass<4>(pl, rp, col0, a0A, a0B, a1A, a1B);
    store_row(out, h0,     w, 10, 4, bv, a0A, a0B);
    store_row(out, h0 + 1, w, 10, 4, bv, a1A, a1B);
}

extern "C" void kernel_launch(void* const* d_in, const int* in_sizes, int n_in,
                              void* d_out, int out_size)
{
    const int*   x      = (const int*)d_in[0];
    const float* weight = (const float*)d_in[1];
    const float* bias   = (const float*)d_in[2];
    float*       out    = (float*)d_out;

    // Build duplicated weight pairs {w,w} in constant memory with two
    // strided D2D 2D-copies (graph-capturable, no allocations).
    void* sym = nullptr;
    cudaGetSymbolAddress(&sym, c_wp);
    char* dst = (char*)sym;
    // x-components
    cudaMemcpy2DAsync(dst,     8, weight, 4, 4, 75, cudaMemcpyDeviceToDevice, 0);
    // y-components
    cudaMemcpy2DAsync(dst + 4, 8, weight, 4, 4, 75, cudaMemcpyDeviceToDevice, 0);

    cudaFuncSetAttribute(conv2dto3d_kernel,
                         cudaFuncAttributeMaxDynamicSharedMemorySize, SMEM_BYTES);

    dim3 grid((OW + TW - 1) / TW, (OH + TH - 1) / TH);   // 16 x 128
    conv2dto3d_kernel<<<grid, NTH, SMEM_BYTES>>>(x, bias, out);
}

// round 16
// speedup vs baseline: 1.1468x; 1.0753x over previous
#include <cuda_runtime.h>
#include <cstdint>

#define IMG_N  2048
#define OW     2044
#define OH     2044
#define TW     128
#define TH     8
#define IR     12          // TH + 4 input rows
#define IC     132         // TW + 4 input cols
#define ICP    136         // padded col stride (bf16 elements)
#define NTH    256

// smem layout (bytes)
#define SX_OFF     0
#define SX_BYTES   (IR * IC * 4)               // 6336: raw int tile
#define PL_OFF     SX_BYTES                    // bf16 planes [IR][9][ICP]
#define PL_BYTES   (IR * 9 * ICP * 2)          // 29376
#define SMEM_BYTES (PL_OFF + PL_BYTES)         // 35712

typedef unsigned long long ull;
typedef unsigned int u32;

__constant__ float c_w[75];                     // weight[d][i][j] = d*25+i*5+j

__device__ __forceinline__ void fma2(ull& acc, ull a, ull b) {
    asm("fma.rn.f32x2 %0, %1, %2, %0;" : "+l"(acc) : "l"(a), "l"(b));
}
// duplicate one float into a f32x2 pair (uniform source -> UR-promotable)
__device__ __forceinline__ ull dup2(float w) {
    ull r; asm("mov.b64 %0, {%1, %1};" : "=l"(r) : "f"(w)); return r;
}
__device__ __forceinline__ ull mkpair_lohi(u32 u) {
    ull r;
    asm("{.reg .b32 a, b;\n\t"
        "shl.b32 a, %1, 16;\n\t"
        "and.b32 b, %1, 0xFFFF0000;\n\t"
        "mov.b64 %0, {a, b};}" : "=l"(r) : "r"(u));
    return r;
}
__device__ __forceinline__ ull mkpair_cross(u32 u, u32 v) {
    ull r;
    asm("{.reg .b32 a, b;\n\t"
        "and.b32 a, %1, 0xFFFF0000;\n\t"
        "shl.b32 b, %2, 16;\n\t"
        "mov.b64 %0, {a, b};}" : "=l"(r) : "r"(u), "r"(v));
    return r;
}

// Expand 9 bit-planes [z0, z0+9) of the int tile into bf16 planes (exact).
__device__ __forceinline__ void expand_planes(const int* __restrict__ sx,
                                              uint16_t* __restrict__ pl,
                                              int tid, int z0)
{
    for (int idx = tid; idx < IR * (IC / 2); idx += NTH) {
        int rr = idx / (IC / 2);
        int c2 = (idx - rr * (IC / 2)) * 2;
        const int* src = sx + rr * IC + c2;
        u32 v0 = (u32)src[0] >> z0;
        u32 v1 = (u32)src[1] >> z0;
        u32* dst = reinterpret_cast<u32*>(pl + (rr * 9) * ICP + c2);
        #pragma unroll
        for (int p = 0; p < 9; p++) {
            u32 val = ((v0 >> p) & 1u) * 0x3F80u
                    | ((v1 >> p) & 1u) * 0x3F800000u;
            dst[p * (ICP / 2)] = val;
        }
    }
}

// One z-pass: 7 outputs from 9 staged planes, 4 cols/thread (w-paired).
// Weights hoisted per-i from constant bank (uniform path).
__device__ __forceinline__ void run_pass(const uint16_t* __restrict__ sp,
                                         int r, int col0, ull* accA, ull* accB)
{
    #pragma unroll
    for (int z = 0; z < 7; z++) { accA[z] = 0ull; accB[z] = 0ull; }

    #pragma unroll 1
    for (int i = 0; i < 5; i++) {
        ull wv[15];
        #pragma unroll
        for (int d = 0; d < 3; d++)
            #pragma unroll
            for (int j = 0; j < 5; j++)
                wv[d * 5 + j] = dup2(c_w[d * 25 + i * 5 + j]);

        const uint16_t* rowi = sp + ((r + i) * 9) * ICP + col0;

        #pragma unroll
        for (int kk = 0; kk < 9; kk++) {
            const u32* rk = reinterpret_cast<const u32*>(rowi + kk * ICP);
            uint2 ma = *reinterpret_cast<const uint2*>(rk);       // bf16 cols 0..3
            uint2 mb = *reinterpret_cast<const uint2*>(rk + 2);   // bf16 cols 4..7

            ull S[7];
            S[0] = mkpair_lohi (ma.x);
            S[1] = mkpair_cross(ma.x, ma.y);
            S[2] = mkpair_lohi (ma.y);
            S[3] = mkpair_cross(ma.y, mb.x);
            S[4] = mkpair_lohi (mb.x);
            S[5] = mkpair_cross(mb.x, mb.y);
            S[6] = mkpair_lohi (mb.y);

            #pragma unroll
            for (int d = 0; d < 3; d++) {
                const int zz = kk - d;                 // compile-time per (kk,d)
                if (zz >= 0 && zz < 7) {
                    #pragma unroll
                    for (int j = 0; j < 5; j++) {
                        const ull w = wv[d * 5 + j];
                        fma2(accA[zz], w, S[j]);       // cols (c, c+1)
                        fma2(accB[zz], w, S[j + 2]);   // cols (c+2, c+3)
                    }
                }
            }
        }
    }
}

__device__ __forceinline__ void store_pass(float* __restrict__ out, int h, int w,
                                           int z0, float bv,
                                           const ull* accA, const ull* accB)
{
    if (h >= OH || w >= OW) return;
    const bool full = (w + 4 <= OW);
    #pragma unroll
    for (int zz = 0; zz < 7; zz++) {
        float2 a = *reinterpret_cast<const float2*>(&accA[zz]);
        float2 b = *reinterpret_cast<const float2*>(&accB[zz]);
        size_t off = ((size_t)(z0 + zz) * OH + h) * OW + w;
        if (full) {
            *reinterpret_cast<float4*>(out + off) =
                make_float4(a.x + bv, a.y + bv, b.x + bv, b.y + bv);
        } else {
            float vals[4] = { a.x + bv, a.y + bv, b.x + bv, b.y + bv };
            #pragma unroll
            for (int c = 0; c < 4; c++)
                if (w + c < OW) out[off + c] = vals[c];
        }
    }
}

__global__ void __launch_bounds__(NTH, 5)
conv2dto3d_kernel(const int* __restrict__ x,
                  const float* __restrict__ bias,
                  float* __restrict__ out)
{
    extern __shared__ unsigned char smem[];
    int*       sx = reinterpret_cast<int*>(smem + SX_OFF);
    uint16_t*  pl = reinterpret_cast<uint16_t*>(smem + PL_OFF);

    const int tid   = threadIdx.x;
    const int wbase = blockIdx.x * TW;
    const int hbase = blockIdx.y * TH;

    // ---- load int tile (clamped) ----
    for (int idx = tid; idx < IR * IC; idx += NTH) {
        int rr = idx / IC, cc = idx - rr * IC;
        int ri = hbase + rr; if (ri > IMG_N - 1) ri = IMG_N - 1;
        int ci = wbase + cc; if (ci > IMG_N - 1) ci = IMG_N - 1;
        sx[idx] = x[ri * IMG_N + ci];
    }
    __syncthreads();

    const int g = tid & 31;
    const int r = tid >> 5;
    const int col0 = g * 4;
    const int h = hbase + r;
    const int w = wbase + col0;
    const float bv = bias[0];

    ull accA[7], accB[7];

    // ---- pass 0: z in [0..6], planes 0..8 ----
    expand_planes(sx, pl, tid, 0);
    __syncthreads();
    run_pass(pl, r, col0, accA, accB);
    __syncthreads();
    store_pass(out, h, w, 0, bv, accA, accB);

    // ---- pass 1: z in [7..13], planes 7..15 ----
    expand_planes(sx, pl, tid, 7);
    __syncthreads();
    run_pass(pl, r, col0, accA, accB);
    store_pass(out, h, w, 7, bv, accA, accB);
}

extern "C" void kernel_launch(void* const* d_in, const int* in_sizes, int n_in,
                              void* d_out, int out_size)
{
    const int*   x      = (const int*)d_in[0];
    const float* weight = (const float*)d_in[1];
    const float* bias   = (const float*)d_in[2];
    float*       out    = (float*)d_out;

    cudaMemcpyToSymbolAsync(c_w, weight, 75 * sizeof(float), 0,
                            cudaMemcpyDeviceToDevice, 0);

    cudaFuncSetAttribute(conv2dto3d_kernel,
                         cudaFuncAttributeMaxDynamicSharedMemorySize, SMEM_BYTES);

    dim3 grid((OW + TW - 1) / TW, (OH + TH - 1) / TH);   // 16 x 256
    conv2dto3d_kernel<<<grid, NTH, SMEM_BYTES>>>(x, bias, out);
}